// round 1
// baseline (speedup 1.0000x reference)
#include <cuda_runtime.h>
#include <cstdint>

#define BATCH 2
#define NPTS 8192
#define IMGS 64
#define KSEL 8
#define RAD2 0.0025f

// Scratch for projected screen-space points (x, y, z, pad). Device global: allocation-free.
__device__ float4 g_screen[BATCH * NPTS];

// ---------------------------------------------------------------------------
// Kernel 1: project points to screen space.
// view = p @ R + T  (row-vector convention), screen = (-f*vx/z, -f*vy/z, z)
// ---------------------------------------------------------------------------
__global__ void project_kernel(const float* __restrict__ pts,
                               const float* __restrict__ Rm,
                               const float* __restrict__ Tv,
                               const float* __restrict__ focal) {
    int t = blockIdx.x * blockDim.x + threadIdx.x;
    if (t >= BATCH * NPTS) return;
    int b = t >> 13;
    const float* p = pts + (size_t)t * 3;
    const float* R = Rm + b * 9;
    const float* T = Tv + b * 3;
    float p0 = p[0], p1 = p[1], p2 = p[2];

    float v0 = __fmaf_rn(p2, R[6], __fmaf_rn(p1, R[3], __fmul_rn(p0, R[0])));
    float v1 = __fmaf_rn(p2, R[7], __fmaf_rn(p1, R[4], __fmul_rn(p0, R[1])));
    float v2 = __fmaf_rn(p2, R[8], __fmaf_rn(p1, R[5], __fmul_rn(p0, R[2])));
    v0 = __fadd_rn(v0, T[0]);
    v1 = __fadd_rn(v1, T[1]);
    float z = __fadd_rn(v2, T[2]);

    float x = -__fdiv_rn(__fmul_rn(focal[0], v0), z);
    float y = -__fdiv_rn(__fmul_rn(focal[1], v1), z);
    g_screen[t] = make_float4(x, y, z, 0.0f);
}

// ---------------------------------------------------------------------------
// Kernel 2: rasterize. One warp per pixel; 512 threads = 16 pixels per block.
// Points staged through shared memory in 2048-point (32KB) chunks.
// Each lane scans NPTS/32 points, keeps sorted top-8 keys ((zbits<<32)|idx),
// then warp-merges 8 rounds of min-reduce+pop.
// ---------------------------------------------------------------------------
#define THREADS 512
#define PIX_PER_BLK 16
#define CHUNK 2048

__global__ __launch_bounds__(THREADS) void raster_kernel(float* __restrict__ out) {
    __shared__ float4 sh[CHUNK];

    const int warp = threadIdx.x >> 5;
    const int lane = threadIdx.x & 31;
    const int blocksPerBatch = (IMGS * IMGS) / PIX_PER_BLK;  // 256
    const int b = blockIdx.x / blocksPerBatch;
    const int pix = (blockIdx.x % blocksPerBatch) * PIX_PER_BLK + warp;  // pixel in batch
    const int py_i = pix >> 6;
    const int px_i = pix & 63;
    // c[i] = 1 - 2*(i+0.5)/64  (exact in fp32)
    const float px = 1.0f - ((float)px_i + 0.5f) * 0.03125f;
    const float py = 1.0f - ((float)py_i + 0.5f) * 0.03125f;

    const unsigned long long SENT = ~0ull;
    unsigned long long key[KSEL];
#pragma unroll
    for (int i = 0; i < KSEL; ++i) key[i] = SENT;

    const float4* __restrict__ base = g_screen + b * NPTS;

    for (int c = 0; c < NPTS / CHUNK; ++c) {
        __syncthreads();
        for (int i = threadIdx.x; i < CHUNK; i += THREADS)
            sh[i] = base[c * CHUNK + i];
        __syncthreads();

#pragma unroll 4
        for (int it = 0; it < CHUNK / 32; ++it) {
            int j = it * 32 + lane;
            float4 s = sh[j];
            float dx = __fsub_rn(px, s.x);
            float dy = __fsub_rn(py, s.y);
            float d2 = __fadd_rn(__fmul_rn(dx, dx), __fmul_rn(dy, dy));
            if (d2 <= RAD2 && s.z > 0.0f) {
                unsigned long long k =
                    ((unsigned long long)__float_as_uint(s.z) << 32) |
                    (unsigned)(c * CHUNK + j);
                if (k < key[KSEL - 1]) {
                    // branchless sorted insert (bubble through ascending list)
                    unsigned long long v = k;
#pragma unroll
                    for (int s2 = 0; s2 < KSEL; ++s2) {
                        unsigned long long cur = key[s2];
                        bool lt = v < cur;
                        key[s2] = lt ? v : cur;
                        v = lt ? cur : v;
                    }
                }
            }
        }
    }

    // Warp merge: 8 rounds of global-min + pop. Keys are unique (idx in low bits),
    // so exactly one lane pops per round; tie-break on idx matches jax top_k stability.
    unsigned long long mysel = SENT;
#pragma unroll
    for (int r = 0; r < KSEL; ++r) {
        unsigned long long m = key[0];
#pragma unroll
        for (int off = 16; off; off >>= 1) {
            unsigned long long o = __shfl_xor_sync(0xffffffffu, m, off);
            if (o < m) m = o;
        }
        if (m != SENT && key[0] == m) {
            // pop: shift left
#pragma unroll
            for (int s2 = 0; s2 < KSEL - 1; ++s2) key[s2] = key[s2 + 1];
            key[KSEL - 1] = SENT;
        }
        if (lane == r) mysel = m;
    }

    // Lanes 0..7 each write one K-slot for this pixel.
    if (lane < KSEL) {
        size_t o = ((size_t)b * (IMGS * IMGS) + pix) * KSEL + lane;
        float vi, vz, vd;
        if (mysel == SENT) {
            vi = -1.0f; vz = -1.0f; vd = -1.0f;
        } else {
            unsigned pidx = (unsigned)mysel;
            float z = __uint_as_float((unsigned)(mysel >> 32));
            float4 s = base[pidx];
            float dx = __fsub_rn(px, s.x);
            float dy = __fsub_rn(py, s.y);
            float d2 = __fadd_rn(__fmul_rn(dx, dx), __fmul_rn(dy, dy));
            vi = (float)pidx; vz = z; vd = d2;
        }
        const size_t TSZ = (size_t)BATCH * IMGS * IMGS * KSEL;  // 65536
        out[o] = vi;             // idx
        out[TSZ + o] = vz;       // zbuf
        out[2 * TSZ + o] = vd;   // dists
    }
}

extern "C" void kernel_launch(void* const* d_in, const int* in_sizes, int n_in,
                              void* d_out, int out_size) {
    const float* pts   = (const float*)d_in[0];  // [2,8192,3]
    const float* Rm    = (const float*)d_in[1];  // [2,3,3]
    const float* Tv    = (const float*)d_in[2];  // [2,3]
    const float* focal = (const float*)d_in[3];  // [2]
    float* out = (float*)d_out;

    project_kernel<<<(BATCH * NPTS + 255) / 256, 256>>>(pts, Rm, Tv, focal);

    int grid = BATCH * (IMGS * IMGS) / PIX_PER_BLK;  // 512
    raster_kernel<<<grid, THREADS>>>(out);
}

// round 2
// speedup vs baseline: 1.3148x; 1.3148x over previous
#include <cuda_runtime.h>
#include <cstdint>

#define BATCH 2
#define NPTS 8192
#define IMGS 64
#define KSEL 8
#define RAD2 0.0025f
#define RADM 0.0501f          // conservative binning radius (margin for fp)

#define NTILE 8               // 8x8 tiles
#define TPX 8                 // 8x8 pixels per tile
#define NBINS (BATCH * NTILE * NTILE)   // 128
#define BINCAP NPTS           // a point enters a tile at most once

// Static scratch (allocation-free). Zero-initialized at module load;
// raster_tile re-zeroes g_cnt at the end of every launch (invariant).
__device__ float4 g_screen[BATCH * NPTS];
__device__ int    g_cnt[NBINS];
__device__ float4 g_bins[NBINS * BINCAP];   // 16 MB

// ---------------------------------------------------------------------------
// Kernel 1: project + scatter into tile bins.
// ---------------------------------------------------------------------------
__global__ __launch_bounds__(256) void project_bin(const float* __restrict__ pts,
                                                   const float* __restrict__ Rm,
                                                   const float* __restrict__ Tv,
                                                   const float* __restrict__ focal) {
    int t = blockIdx.x * 256 + threadIdx.x;
    if (t >= BATCH * NPTS) return;
    int b = t >> 13;
    int n = t & (NPTS - 1);
    const float* p = pts + (size_t)t * 3;
    const float* R = Rm + b * 9;
    const float* T = Tv + b * 3;
    float p0 = p[0], p1 = p[1], p2 = p[2];

    float v0 = __fmaf_rn(p2, R[6], __fmaf_rn(p1, R[3], __fmul_rn(p0, R[0])));
    float v1 = __fmaf_rn(p2, R[7], __fmaf_rn(p1, R[4], __fmul_rn(p0, R[1])));
    float v2 = __fmaf_rn(p2, R[8], __fmaf_rn(p1, R[5], __fmul_rn(p0, R[2])));
    v0 = __fadd_rn(v0, T[0]);
    v1 = __fadd_rn(v1, T[1]);
    float z = __fadd_rn(v2, T[2]);

    float x = -__fdiv_rn(__fmul_rn(focal[0], v0), z);
    float y = -__fdiv_rn(__fmul_rn(focal[1], v1), z);
    g_screen[t] = make_float4(x, y, z, 0.0f);

    if (!(z > 0.0f)) return;

    // pixel centers: c(i) = 1 - (i+0.5)/32, decreasing in i.
    // |c(i) - x| <= RADM  =>  i in [ceil(32(1-x-RADM)-0.5), floor(32(1-x+RADM)-0.5)]
    int ix0 = (int)ceilf(__fmul_rn(1.0f - (x + RADM), 32.0f) - 0.5f);
    int ix1 = (int)floorf(__fmul_rn(1.0f - (x - RADM), 32.0f) - 0.5f);
    int iy0 = (int)ceilf(__fmul_rn(1.0f - (y + RADM), 32.0f) - 0.5f);
    int iy1 = (int)floorf(__fmul_rn(1.0f - (y - RADM), 32.0f) - 0.5f);
    ix0 = max(ix0, 0); ix1 = min(ix1, IMGS - 1);
    iy0 = max(iy0, 0); iy1 = min(iy1, IMGS - 1);
    if (ix0 > ix1 || iy0 > iy1) return;

    int tx0 = ix0 >> 3, tx1 = ix1 >> 3;
    int ty0 = iy0 >> 3, ty1 = iy1 >> 3;
    float4 rec = make_float4(x, y, z, __int_as_float(n));
    for (int ty = ty0; ty <= ty1; ++ty)
        for (int tx = tx0; tx <= tx1; ++tx) {
            int tb = b * (NTILE * NTILE) + ty * NTILE + tx;
            int pos = atomicAdd(&g_cnt[tb], 1);
            g_bins[tb * BINCAP + pos] = rec;
        }
}

// ---------------------------------------------------------------------------
// Kernel 2: per-tile raster. One block per (batch,tile); 256 threads.
// Pixel layout: warp w owns pixel row w of the tile; lane&7 = column,
// lane>>3 = sub (4 lanes cooperate per pixel, scanning j ≡ sub (mod 4)).
// ---------------------------------------------------------------------------
#define RTHREADS 256
#define RCHUNK 512

__global__ __launch_bounds__(RTHREADS) void raster_tile(float* __restrict__ out) {
    __shared__ float4 sh[RCHUNK];

    const int bt = blockIdx.x;             // 0..127
    const int b = bt >> 6;
    const int tile = bt & 63;
    const int ty = tile >> 3, tx = tile & 7;
    const int warp = threadIdx.x >> 5;     // 0..7 = pixel row in tile
    const int lane = threadIdx.x & 31;
    const int col = lane & 7;
    const int sub = lane >> 3;

    const int py_i = ty * TPX + warp;
    const int px_i = tx * TPX + col;
    const float px = 1.0f - ((float)px_i + 0.5f) * 0.03125f;
    const float py = 1.0f - ((float)py_i + 0.5f) * 0.03125f;

    const int cnt = g_cnt[bt];
    const float4* __restrict__ bin = g_bins + (size_t)bt * BINCAP;

    const unsigned long long SENT = ~0ull;
    unsigned long long key[KSEL];
#pragma unroll
    for (int i = 0; i < KSEL; ++i) key[i] = SENT;

    for (int c0 = 0; c0 < cnt; c0 += RCHUNK) {
        int nn = min(RCHUNK, cnt - c0);
        __syncthreads();
        for (int i = threadIdx.x; i < nn; i += RTHREADS)
            sh[i] = bin[c0 + i];
        __syncthreads();

        for (int j = sub; j < nn; j += 4) {
            float4 s = sh[j];
            float dx = __fsub_rn(px, s.x);
            float dy = __fsub_rn(py, s.y);
            float d2 = __fadd_rn(__fmul_rn(dx, dx), __fmul_rn(dy, dy));
            if (d2 <= RAD2 && s.z > 0.0f) {
                unsigned long long k =
                    ((unsigned long long)__float_as_uint(s.z) << 32) |
                    (unsigned)__float_as_int(s.w);
                if (k < key[KSEL - 1]) {
                    unsigned long long v = k;
#pragma unroll
                    for (int s2 = 0; s2 < KSEL; ++s2) {
                        unsigned long long cur = key[s2];
                        bool lt = v < cur;
                        key[s2] = lt ? v : cur;
                        v = lt ? cur : v;
                    }
                }
            }
        }
    }

    // Merge the 4 sub-lists of each pixel: 8 rounds of min + pop.
    // Lanes {l, l^8, l^16, l^24} share a pixel; keys are globally unique.
    unsigned long long res[KSEL];
#pragma unroll
    for (int r = 0; r < KSEL; ++r) {
        unsigned long long m = key[0];
        unsigned long long o = __shfl_xor_sync(0xffffffffu, m, 8);
        if (o < m) m = o;
        o = __shfl_xor_sync(0xffffffffu, m, 16);
        if (o < m) m = o;
        if (m != SENT && key[0] == m) {
#pragma unroll
            for (int s2 = 0; s2 < KSEL - 1; ++s2) key[s2] = key[s2 + 1];
            key[KSEL - 1] = SENT;
        }
        res[r] = m;
    }

    if (sub == 0) {
        const float4* __restrict__ base = g_screen + b * NPTS;
        const size_t pix = (size_t)py_i * IMGS + px_i;
        const size_t TSZ = (size_t)BATCH * IMGS * IMGS * KSEL;  // 65536
        const size_t o0 = ((size_t)b * (IMGS * IMGS) + pix) * KSEL;
#pragma unroll
        for (int r = 0; r < KSEL; ++r) {
            float vi, vz, vd;
            if (res[r] == SENT) {
                vi = -1.0f; vz = -1.0f; vd = -1.0f;
            } else {
                unsigned pidx = (unsigned)res[r];
                float4 s = base[pidx];
                float dx = __fsub_rn(px, s.x);
                float dy = __fsub_rn(py, s.y);
                vd = __fadd_rn(__fmul_rn(dx, dx), __fmul_rn(dy, dy));
                vz = __uint_as_float((unsigned)(res[r] >> 32));
                vi = (float)pidx;
            }
            out[o0 + r] = vi;
            out[TSZ + o0 + r] = vz;
            out[2 * TSZ + o0 + r] = vd;
        }
    }

    // Restore zero-state for the next launch (graph replay invariant).
    __syncthreads();
    if (threadIdx.x == 0) g_cnt[bt] = 0;
}

extern "C" void kernel_launch(void* const* d_in, const int* in_sizes, int n_in,
                              void* d_out, int out_size) {
    const float* pts   = (const float*)d_in[0];  // [2,8192,3]
    const float* Rm    = (const float*)d_in[1];  // [2,3,3]
    const float* Tv    = (const float*)d_in[2];  // [2,3]
    const float* focal = (const float*)d_in[3];  // [2]
    float* out = (float*)d_out;

    project_bin<<<(BATCH * NPTS + 255) / 256, 256>>>(pts, Rm, Tv, focal);
    raster_tile<<<NBINS, RTHREADS>>>(out);
}

// round 3
// speedup vs baseline: 3.2169x; 2.4468x over previous
#include <cuda_runtime.h>
#include <cstdint>

#define BATCH 2
#define NPTS 8192
#define IMGS 64
#define KSEL 8
#define RAD2 0.0025f
#define RADM 0.0501f            // conservative bbox radius
#define NPIX (BATCH * IMGS * IMGS)   // 8192
#define CAP 1024                // per-pixel candidate capacity (>>80 sigma of expected ~120)

// Static scratch (allocation-free). BSS-zero at load; kernel B restores
// g_cnt to zero each launch (graph-replay invariant).
__device__ float4 g_screen[BATCH * NPTS];
__device__ int g_cnt[NPIX];
__device__ unsigned long long g_plist[(size_t)NPIX * CAP];   // 64 MB

// ---------------------------------------------------------------------------
// Kernel A: project points; scatter exact-test candidates into per-pixel lists.
// ---------------------------------------------------------------------------
__global__ __launch_bounds__(256) void project_scatter(const float* __restrict__ pts,
                                                       const float* __restrict__ Rm,
                                                       const float* __restrict__ Tv,
                                                       const float* __restrict__ focal) {
    int t = blockIdx.x * 256 + threadIdx.x;
    if (t >= BATCH * NPTS) return;
    int b = t >> 13;
    int n = t & (NPTS - 1);
    const float* p = pts + (size_t)t * 3;
    const float* R = Rm + b * 9;
    const float* T = Tv + b * 3;
    float p0 = p[0], p1 = p[1], p2 = p[2];

    float v0 = __fmaf_rn(p2, R[6], __fmaf_rn(p1, R[3], __fmul_rn(p0, R[0])));
    float v1 = __fmaf_rn(p2, R[7], __fmaf_rn(p1, R[4], __fmul_rn(p0, R[1])));
    float v2 = __fmaf_rn(p2, R[8], __fmaf_rn(p1, R[5], __fmul_rn(p0, R[2])));
    v0 = __fadd_rn(v0, T[0]);
    v1 = __fadd_rn(v1, T[1]);
    float z = __fadd_rn(v2, T[2]);

    float x = -__fdiv_rn(__fmul_rn(focal[0], v0), z);
    float y = -__fdiv_rn(__fmul_rn(focal[1], v1), z);
    g_screen[t] = make_float4(x, y, z, 0.0f);

    if (!(z > 0.0f)) return;

    // pixel centers c(i) = 1 - (i+0.5)*0.03125, decreasing in i.
    // |c(i) - x| <= RADM  =>  i in [ceil(32(1-x-RADM)-0.5), floor(32(1-x+RADM)-0.5)]
    int ix0 = (int)ceilf(__fmul_rn(1.0f - (x + RADM), 32.0f) - 0.5f);
    int ix1 = (int)floorf(__fmul_rn(1.0f - (x - RADM), 32.0f) - 0.5f);
    int iy0 = (int)ceilf(__fmul_rn(1.0f - (y + RADM), 32.0f) - 0.5f);
    int iy1 = (int)floorf(__fmul_rn(1.0f - (y - RADM), 32.0f) - 0.5f);
    ix0 = max(ix0, 0); ix1 = min(ix1, IMGS - 1);
    iy0 = max(iy0, 0); iy1 = min(iy1, IMGS - 1);
    if (ix0 > ix1 || iy0 > iy1) return;

    unsigned long long key =
        ((unsigned long long)__float_as_uint(z) << 32) | (unsigned)n;

    for (int iy = iy0; iy <= iy1; ++iy) {
        float py = 1.0f - ((float)iy + 0.5f) * 0.03125f;
        float dy = __fsub_rn(py, y);
        float dy2 = __fmul_rn(dy, dy);
        for (int ix = ix0; ix <= ix1; ++ix) {
            float px = 1.0f - ((float)ix + 0.5f) * 0.03125f;
            float dx = __fsub_rn(px, x);
            float d2 = __fadd_rn(__fmul_rn(dx, dx), dy2);
            if (d2 <= RAD2) {   // exact reference predicate (z>0 already known)
                int pix = (b << 12) + (iy << 6) + ix;
                int pos = atomicAdd(&g_cnt[pix], 1);
                if (pos < CAP)
                    g_plist[(size_t)pix * CAP + pos] = key;
            }
        }
    }
}

// ---------------------------------------------------------------------------
// Kernel B: one warp per pixel — top-8 selection from the pixel's list.
// ---------------------------------------------------------------------------
__global__ __launch_bounds__(256) void select_k(float* __restrict__ out) {
    const int warp = threadIdx.x >> 5;
    const int lane = threadIdx.x & 31;
    const int pix = blockIdx.x * 8 + warp;          // 0..NPIX-1
    const int b = pix >> 12;
    const int pp = pix & 4095;
    const int py_i = pp >> 6;
    const int px_i = pp & 63;

    const int cnt = min(g_cnt[pix], CAP);
    const unsigned long long* __restrict__ list = g_plist + (size_t)pix * CAP;

    const unsigned long long SENT = ~0ull;
    unsigned long long key[KSEL];
#pragma unroll
    for (int i = 0; i < KSEL; ++i) key[i] = SENT;

    // strided scan; per-lane sorted top-8
    for (int j = lane; j < cnt; j += 32) {
        unsigned long long k = list[j];
        if (k < key[KSEL - 1]) {
            unsigned long long v = k;
#pragma unroll
            for (int s2 = 0; s2 < KSEL; ++s2) {
                unsigned long long cur = key[s2];
                bool lt = v < cur;
                key[s2] = lt ? v : cur;
                v = lt ? cur : v;
            }
        }
    }

    // 8 rounds of warp-wide min + pop. Keys unique (idx in low bits) =>
    // exactly one lane pops; tie-break = lowest idx, matching jax top_k.
    unsigned long long mysel = SENT;
#pragma unroll
    for (int r = 0; r < KSEL; ++r) {
        unsigned long long m = key[0];
#pragma unroll
        for (int off = 16; off; off >>= 1) {
            unsigned long long o = __shfl_xor_sync(0xffffffffu, m, off);
            if (o < m) m = o;
        }
        if (m != SENT && key[0] == m) {
#pragma unroll
            for (int s2 = 0; s2 < KSEL - 1; ++s2) key[s2] = key[s2 + 1];
            key[KSEL - 1] = SENT;
        }
        if (lane == r) mysel = m;
    }

    if (lane < KSEL) {
        const float px = 1.0f - ((float)px_i + 0.5f) * 0.03125f;
        const float py = 1.0f - ((float)py_i + 0.5f) * 0.03125f;
        float vi, vz, vd;
        if (mysel == SENT) {
            vi = -1.0f; vz = -1.0f; vd = -1.0f;
        } else {
            unsigned pidx = (unsigned)mysel;
            float4 s = g_screen[(b << 13) + pidx];
            float dx = __fsub_rn(px, s.x);
            float dy = __fsub_rn(py, s.y);
            vd = __fadd_rn(__fmul_rn(dx, dx), __fmul_rn(dy, dy));
            vz = __uint_as_float((unsigned)(mysel >> 32));
            vi = (float)pidx;
        }
        const size_t TSZ = (size_t)NPIX * KSEL;     // 65536
        const size_t o0 = (size_t)pix * KSEL + lane;
        out[o0] = vi;
        out[TSZ + o0] = vz;
        out[2 * TSZ + o0] = vd;
    }

    if (lane == 0) g_cnt[pix] = 0;   // restore zero-state for next replay
}

extern "C" void kernel_launch(void* const* d_in, const int* in_sizes, int n_in,
                              void* d_out, int out_size) {
    const float* pts   = (const float*)d_in[0];  // [2,8192,3]
    const float* Rm    = (const float*)d_in[1];  // [2,3,3]
    const float* Tv    = (const float*)d_in[2];  // [2,3]
    const float* focal = (const float*)d_in[3];  // [2]
    float* out = (float*)d_out;

    project_scatter<<<(BATCH * NPTS + 255) / 256, 256>>>(pts, Rm, Tv, focal);
    select_k<<<NPIX / 8, 256>>>(out);
}

// round 4
// speedup vs baseline: 4.2126x; 1.3095x over previous
#include <cuda_runtime.h>
#include <cstdint>

#define BATCH 2
#define NPTS 8192
#define IMGS 64
#define KSEL 8
#define RAD2 0.0025f
#define RADM 0.0501f            // conservative bbox radius
#define NPIX (BATCH * IMGS * IMGS)   // 8192
#define CAP 512                 // per-pixel capacity (expected hot-pixel ~120)

// Static scratch (allocation-free). BSS-zero at load; kernel B restores
// g_cnt to zero each launch (graph-replay invariant).
__device__ float4 g_screen[BATCH * NPTS];
__device__ int g_cnt[NPIX];
__device__ unsigned long long g_plist[(size_t)NPIX * CAP];   // 32 MB

// ---------------------------------------------------------------------------
// Kernel A: project; scatter exact-test candidates into per-pixel lists.
// Fixed 4x4 unrolled bbox loop -> independent atomic+store pairs (MLP).
// ---------------------------------------------------------------------------
__global__ __launch_bounds__(128) void project_scatter(const float* __restrict__ pts,
                                                       const float* __restrict__ Rm,
                                                       const float* __restrict__ Tv,
                                                       const float* __restrict__ focal) {
    int t = blockIdx.x * 128 + threadIdx.x;
    if (t >= BATCH * NPTS) return;
    int b = t >> 13;
    int n = t & (NPTS - 1);
    const float* p = pts + (size_t)t * 3;
    const float* R = Rm + b * 9;
    const float* T = Tv + b * 3;
    float p0 = p[0], p1 = p[1], p2 = p[2];

    float v0 = __fmaf_rn(p2, R[6], __fmaf_rn(p1, R[3], __fmul_rn(p0, R[0])));
    float v1 = __fmaf_rn(p2, R[7], __fmaf_rn(p1, R[4], __fmul_rn(p0, R[1])));
    float v2 = __fmaf_rn(p2, R[8], __fmaf_rn(p1, R[5], __fmul_rn(p0, R[2])));
    v0 = __fadd_rn(v0, T[0]);
    v1 = __fadd_rn(v1, T[1]);
    float z = __fadd_rn(v2, T[2]);

    float x = -__fdiv_rn(__fmul_rn(focal[0], v0), z);
    float y = -__fdiv_rn(__fmul_rn(focal[1], v1), z);
    g_screen[t] = make_float4(x, y, z, 0.0f);

    if (!(z > 0.0f)) return;

    // pixel centers c(i) = 1 - (i+0.5)*0.03125, decreasing in i.
    int ix0 = (int)ceilf(__fmul_rn(1.0f - (x + RADM), 32.0f) - 0.5f);
    int ix1 = (int)floorf(__fmul_rn(1.0f - (x - RADM), 32.0f) - 0.5f);
    int iy0 = (int)ceilf(__fmul_rn(1.0f - (y + RADM), 32.0f) - 0.5f);
    int iy1 = (int)floorf(__fmul_rn(1.0f - (y - RADM), 32.0f) - 0.5f);
    ix0 = max(ix0, 0); ix1 = min(ix1, IMGS - 1);
    iy0 = max(iy0, 0); iy1 = min(iy1, IMGS - 1);
    if (ix0 > ix1 || iy0 > iy1) return;

    unsigned long long key =
        ((unsigned long long)__float_as_uint(z) << 32) | (unsigned)n;

    // bbox spans at most 4x4 pixel centers (0.1002/0.03125 = 3.2 pitches).
    // Fully unrolled predicated loop: the atomic+store pairs are independent,
    // so up to 16 ATOMG are in flight at once instead of a serial chain.
#pragma unroll
    for (int a = 0; a < 4; ++a) {
        int iy = iy0 + a;
        bool vy = iy <= iy1;
        float py = 1.0f - ((float)iy + 0.5f) * 0.03125f;
        float dy = __fsub_rn(py, y);
        float dy2 = __fmul_rn(dy, dy);
#pragma unroll
        for (int c = 0; c < 4; ++c) {
            int ix = ix0 + c;
            bool vx = ix <= ix1;
            float px = 1.0f - ((float)ix + 0.5f) * 0.03125f;
            float dx = __fsub_rn(px, x);
            float d2 = __fadd_rn(__fmul_rn(dx, dx), dy2);
            if (vy && vx && d2 <= RAD2) {     // exact reference predicate
                int pix = (b << 12) + (iy << 6) + ix;
                int pos = atomicAdd(&g_cnt[pix], 1);
                if (pos < CAP)
                    g_plist[(size_t)pix * CAP + pos] = key;
            }
        }
    }
}

// ---------------------------------------------------------------------------
// Kernel B: one warp per pixel — top-8 selection.
//   cnt == 0   : write -1s, done.
//   cnt <= 32  : warp bitonic sort (1 key/lane), lanes 0..7 emit.
//   cnt  > 32  : per-lane sorted top-8 + 8 rounds of warp min+pop.
// Keys are unique ((zbits<<32)|idx) => order = (z, idx) asc = jax top_k order.
// ---------------------------------------------------------------------------
__global__ __launch_bounds__(256) void select_k(float* __restrict__ out) {
    const int warp = threadIdx.x >> 5;
    const int lane = threadIdx.x & 31;
    const int pix = blockIdx.x * 8 + warp;          // 0..NPIX-1
    const int b = pix >> 12;
    const int pp = pix & 4095;
    const int py_i = pp >> 6;
    const int px_i = pp & 63;

    const int cnt = min(g_cnt[pix], CAP);
    const size_t TSZ = (size_t)NPIX * KSEL;         // 65536
    const size_t o0 = (size_t)pix * KSEL + lane;
    const unsigned long long SENT = ~0ull;

    if (cnt == 0) {
        if (lane < KSEL) {
            out[o0] = -1.0f;
            out[TSZ + o0] = -1.0f;
            out[2 * TSZ + o0] = -1.0f;
        }
        return;
    }

    const unsigned long long* __restrict__ list = g_plist + (size_t)pix * CAP;
    unsigned long long mysel;

    if (cnt <= 32) {
        // ---- bitonic sort of 32 keys (pad with SENT), ascending ----
        unsigned long long v = (lane < cnt) ? list[lane] : SENT;
#pragma unroll
        for (int k = 2; k <= 32; k <<= 1) {
#pragma unroll
            for (int j = k >> 1; j > 0; j >>= 1) {
                unsigned long long o = __shfl_xor_sync(0xffffffffu, v, j);
                bool up = ((lane & k) == 0);      // block sort direction
                bool lower = ((lane & j) == 0);   // lane is lower partner
                bool takeMin = (lower == up);
                bool oLess = o < v;
                v = (takeMin == oLess) ? o : v;   // takeMin? min : max
            }
        }
        mysel = v;                                // lane r holds r-th smallest
    } else {
        // ---- per-lane sorted top-8 over strided scan ----
        unsigned long long key[KSEL];
#pragma unroll
        for (int i = 0; i < KSEL; ++i) key[i] = SENT;
        for (int j = lane; j < cnt; j += 32) {
            unsigned long long k = list[j];
            if (k < key[KSEL - 1]) {
                unsigned long long v = k;
#pragma unroll
                for (int s2 = 0; s2 < KSEL; ++s2) {
                    unsigned long long cur = key[s2];
                    bool lt = v < cur;
                    key[s2] = lt ? v : cur;
                    v = lt ? cur : v;
                }
            }
        }
        // ---- 8 rounds of warp min + pop (unique keys => one pop/round) ----
        mysel = SENT;
#pragma unroll
        for (int r = 0; r < KSEL; ++r) {
            unsigned long long m = key[0];
#pragma unroll
            for (int off = 16; off; off >>= 1) {
                unsigned long long o = __shfl_xor_sync(0xffffffffu, m, off);
                if (o < m) m = o;
            }
            if (m != SENT && key[0] == m) {
#pragma unroll
                for (int s2 = 0; s2 < KSEL - 1; ++s2) key[s2] = key[s2 + 1];
                key[KSEL - 1] = SENT;
            }
            if (lane == r) mysel = m;
        }
    }

    if (lane < KSEL) {
        const float px = 1.0f - ((float)px_i + 0.5f) * 0.03125f;
        const float py = 1.0f - ((float)py_i + 0.5f) * 0.03125f;
        float vi, vz, vd;
        if (mysel == SENT) {
            vi = -1.0f; vz = -1.0f; vd = -1.0f;
        } else {
            unsigned pidx = (unsigned)mysel;
            float4 s = g_screen[(b << 13) + pidx];
            float dx = __fsub_rn(px, s.x);
            float dy = __fsub_rn(py, s.y);
            vd = __fadd_rn(__fmul_rn(dx, dx), __fmul_rn(dy, dy));
            vz = __uint_as_float((unsigned)(mysel >> 32));
            vi = (float)pidx;
        }
        out[o0] = vi;
        out[TSZ + o0] = vz;
        out[2 * TSZ + o0] = vd;
    }

    if (lane == 0) g_cnt[pix] = 0;   // restore zero-state for next replay
}

extern "C" void kernel_launch(void* const* d_in, const int* in_sizes, int n_in,
                              void* d_out, int out_size) {
    const float* pts   = (const float*)d_in[0];  // [2,8192,3]
    const float* Rm    = (const float*)d_in[1];  // [2,3,3]
    const float* Tv    = (const float*)d_in[2];  // [2,3]
    const float* focal = (const float*)d_in[3];  // [2]
    float* out = (float*)d_out;

    project_scatter<<<(BATCH * NPTS + 127) / 128, 128>>>(pts, Rm, Tv, focal);
    select_k<<<NPIX / 8, 256>>>(out);
}